// round 14
// baseline (speedup 1.0000x reference)
#include <cuda_runtime.h>
#include <cuda_fp16.h>
#include <math.h>
#include <stdint.h>

#define NNODES 40962
#define NEDGES 327680
#define D 512
#define K1 1024
#define MPAD 41088  // 321*128

// Scratch (device globals; no allocations allowed)
__device__ float  g_edge_sum[(size_t)NNODES * D];   // 84 MB fp32 accum
__device__ __half g_x[(size_t)MPAD * K1];           // 84 MB  [node|edge_sum] fp16
__device__ __half g_h[(size_t)MPAD * D];            // 42 MB  hidden fp16
__device__ __half g_w1t[(size_t)D * K1];            // W1^T [n=512][k=1024] fp16
__device__ __half g_w2t[(size_t)D * D];             // W2^T [n=512][k=512]  fp16

__device__ __forceinline__ void mma_f16(float* c, const unsigned* a, const unsigned* b) {
    asm volatile(
        "mma.sync.aligned.m16n8k16.row.col.f32.f16.f16.f32 "
        "{%0,%1,%2,%3}, {%4,%5,%6,%7}, {%8,%9}, {%0,%1,%2,%3};\n"
        : "+f"(c[0]), "+f"(c[1]), "+f"(c[2]), "+f"(c[3])
        : "r"(a[0]), "r"(a[1]), "r"(a[2]), "r"(a[3]), "r"(b[0]), "r"(b[1]));
}
__device__ __forceinline__ void ldsm4(unsigned& r0, unsigned& r1, unsigned& r2,
                                      unsigned& r3, unsigned saddr) {
    asm volatile("ldmatrix.sync.aligned.m8n8.x4.shared.b16 {%0,%1,%2,%3}, [%4];"
                 : "=r"(r0), "=r"(r1), "=r"(r2), "=r"(r3) : "r"(saddr));
}
__device__ __forceinline__ void cp16(void* sdst, const void* gsrc) {
    unsigned sa = (unsigned)__cvta_generic_to_shared(sdst);
    asm volatile("cp.async.cg.shared.global [%0], [%1], 16;\n" :: "r"(sa), "l"(gsrc));
}
#define CP_COMMIT() asm volatile("cp.async.commit_group;\n")
#define CP_WAIT2()  asm volatile("cp.async.wait_group 2;\n")

__device__ __forceinline__ unsigned h2u(__half2 h) {
    return *reinterpret_cast<unsigned*>(&h);
}
__device__ __forceinline__ void redv4(float* dst, float4 v) {
    asm volatile("red.global.add.v4.f32 [%0], {%1,%2,%3,%4};\n"
                 :: "l"(dst), "f"(v.x), "f"(v.y), "f"(v.z), "f"(v.w) : "memory");
}

// ---------------------------------------------------------------------------
__global__ void zero_kernel() {
    size_t i = (size_t)blockIdx.x * blockDim.x + threadIdx.x;
    size_t n4 = (size_t)NNODES * D / 4;
    if (i < n4) reinterpret_cast<float4*>(g_edge_sum)[i] = make_float4(0.f, 0.f, 0.f, 0.f);
}

// Column-split scatter, 4 edges per thread (MLP=4).
// Pass handles columns [col0, col0+256); RMW slice 42MB stays L2-resident
// under the .cs streaming loads.
__global__ __launch_bounds__(256) void scatter_kernel(const float* __restrict__ edge_attr,
                                                      const int* __restrict__ edge_index,
                                                      int col0) {
    int idx = blockIdx.x * 256 + threadIdx.x;
    int p = idx >> 6;              // edge quad
    int t = idx & 63;              // float4 slot within the 256-col half
    int e0 = p * 4;
    int4 rr = *reinterpret_cast<const int4*>(edge_index + NEDGES + e0);
    const float* s0 = edge_attr + (size_t)e0 * D + col0 + t * 4;
    float4 v0 = __ldcs(reinterpret_cast<const float4*>(s0));
    float4 v1 = __ldcs(reinterpret_cast<const float4*>(s0 + D));
    float4 v2 = __ldcs(reinterpret_cast<const float4*>(s0 + 2 * D));
    float4 v3 = __ldcs(reinterpret_cast<const float4*>(s0 + 3 * D));
    int co = col0 + t * 4;
    redv4(g_edge_sum + (size_t)rr.x * D + co, v0);
    redv4(g_edge_sum + (size_t)rr.y * D + co, v1);
    redv4(g_edge_sum + (size_t)rr.z * D + co, v2);
    redv4(g_edge_sum + (size_t)rr.w * D + co, v3);
}

// W1 [k=1024][n=512] -> g_w1t [n][k] fp16
__global__ void convw1t_kernel(const float* __restrict__ W1) {
    __shared__ float t[32][33];
    int bx = blockIdx.x;   // k tile (32 tiles)
    int by = blockIdx.y;   // n tile (16 tiles)
    int x = threadIdx.x, y = threadIdx.y;  // 32 x 8
#pragma unroll
    for (int i = 0; i < 32; i += 8)
        t[y + i][x] = W1[(size_t)(bx * 32 + y + i) * D + by * 32 + x];
    __syncthreads();
#pragma unroll
    for (int i = 0; i < 32; i += 8)
        g_w1t[(size_t)(by * 32 + y + i) * K1 + bx * 32 + x] = __float2half_rn(t[x][y + i]);
}

// W2 [k=512][n=512] -> g_w2t [n][k] fp16
__global__ void convw2t_kernel(const float* __restrict__ W2) {
    __shared__ float t[32][33];
    int bx = blockIdx.x;   // k tile (16)
    int by = blockIdx.y;   // n tile (16)
    int x = threadIdx.x, y = threadIdx.y;
#pragma unroll
    for (int i = 0; i < 32; i += 8)
        t[y + i][x] = W2[(size_t)(bx * 32 + y + i) * D + by * 32 + x];
    __syncthreads();
#pragma unroll
    for (int i = 0; i < 32; i += 8)
        g_w2t[(size_t)(by * 32 + y + i) * D + bx * 32 + x] = __float2half_rn(t[x][y + i]);
}

// g_x[r] = fp16([node[r] | edge_sum[r]]), zero for pad rows
__global__ void pack_kernel(const float* __restrict__ node) {
    int r = blockIdx.x;
    int c = threadIdx.x * 4;
    float4 v = make_float4(0.f, 0.f, 0.f, 0.f);
    if (r < NNODES) {
        v = (c < D)
            ? *reinterpret_cast<const float4*>(node + (size_t)r * D + c)
            : *reinterpret_cast<const float4*>(g_edge_sum + (size_t)r * D + (c - D));
    }
    __half2 h01 = __floats2half2_rn(v.x, v.y);
    __half2 h23 = __floats2half2_rn(v.z, v.w);
    uint2 o = make_uint2(h2u(h01), h2u(h23));
    *reinterpret_cast<uint2*>(g_x + (size_t)r * K1 + c) = o;
}

// ---------------------------------------------------------------------------
// GEMM1: h = silu(g_x @ W1 + b1)   M=MPAD K=1024 N=512, fp16 mma m16n8k16.
// BM=128 BN=128 BK=32. 256 thr, 8 warps (2m x 4n), warp tile 64x32.
// A,B smem tiles: [128 rows][16 half2 words], word stride 20.
// ldmatrix frag loads. 4-stage cp.async; next stage issued BEFORE the mma
// burst (stage kt+3 aliases the kt-1 buffer, already fenced by the sync).
// ---------------------------------------------------------------------------
#define G1_RS 20                  // row stride in 32-bit words
#define G1_TILE (128 * G1_RS)     // words per operand tile
#define G1_STW (2 * G1_TILE)      // words per stage (A+B)
__global__ __launch_bounds__(256, 2) void gemm1_f16(const float* __restrict__ b1) {
    extern __shared__ unsigned smw[];
    int tid = threadIdx.x, lane = tid & 31, wid = tid >> 5;
    int warp_m = wid >> 2, warp_n = wid & 3;
    int g = lane >> 2, tig = lane & 3;
    int bx = blockIdx.x, by = blockIdx.y;

    unsigned sbase = (unsigned)__cvta_generic_to_shared(smw);

    // ldmatrix lane-address components
    int t4 = lane >> 3, rr = lane & 7;
    int a_row = (t4 & 1) * 8 + rr;     // row offset within mtile
    int a_wof = (t4 >> 1) * 4;         // word offset within ks group
    int b_row = (t4 >> 1) * 8 + rr;    // row offset within ntile-pair
    int b_wof = (t4 & 1) * 4;

    const __half* aSrc = g_x + (size_t)(by * 128) * K1;
    const __half* bSrc = g_w1t + (size_t)(bx * 128) * K1;

    float acc[4][4][4] = {};

#define G1_ISSUE(kt, st)                                                         \
    {                                                                            \
        unsigned* base = smw + (st) * G1_STW;                                    \
        _Pragma("unroll")                                                        \
        for (int t = 0; t < 2; ++t) {                                            \
            int idx = tid + t * 256;                                             \
            int row = idx >> 2, wq = (idx & 3) * 4;                              \
            cp16(base + row * G1_RS + wq,                                        \
                 aSrc + (size_t)row * K1 + (kt) * 32 + wq * 2);                  \
        }                                                                        \
        _Pragma("unroll")                                                        \
        for (int t = 0; t < 2; ++t) {                                            \
            int idx = tid + t * 256;                                             \
            int row = idx >> 2, wq = (idx & 3) * 4;                              \
            cp16(base + G1_TILE + row * G1_RS + wq,                              \
                 bSrc + (size_t)row * K1 + (kt) * 32 + wq * 2);                  \
        }                                                                        \
        CP_COMMIT();                                                             \
    }

    G1_ISSUE(0, 0);
    G1_ISSUE(1, 1);
    G1_ISSUE(2, 2);

    for (int kt = 0; kt < 32; ++kt) {
        CP_WAIT2();
        __syncthreads();
        // issue next stage first: overlaps GMEM loads with the mma burst
        if (kt + 3 < 32) {
            G1_ISSUE(kt + 3, (kt + 3) & 3);
        } else {
            CP_COMMIT();
        }
        unsigned cbase = sbase + ((kt & 3) * G1_STW) * 4;
#pragma unroll
        for (int ks = 0; ks < 2; ++ks) {
            unsigned a[4][4], b[4][2];
#pragma unroll
            for (int i = 0; i < 4; ++i) {
                unsigned addr = cbase +
                    ((warp_m * 64 + i * 16 + a_row) * G1_RS + ks * 8 + a_wof) * 4;
                ldsm4(a[i][0], a[i][1], a[i][2], a[i][3], addr);
            }
#pragma unroll
            for (int j2 = 0; j2 < 2; ++j2) {
                unsigned addr = cbase +
                    (G1_TILE + (warp_n * 32 + j2 * 16 + b_row) * G1_RS + ks * 8 + b_wof) * 4;
                ldsm4(b[2 * j2][0], b[2 * j2][1], b[2 * j2 + 1][0], b[2 * j2 + 1][1], addr);
            }
#pragma unroll
            for (int i = 0; i < 4; ++i)
#pragma unroll
                for (int j = 0; j < 4; ++j)
                    mma_f16(acc[i][j], a[i], b[j]);
        }
    }

    // epilogue: bias + silu -> fp16 g_h
#pragma unroll
    for (int i = 0; i < 4; ++i) {
        int r0 = by * 128 + warp_m * 64 + i * 16 + g;
#pragma unroll
        for (int j = 0; j < 4; ++j) {
            int c0 = bx * 128 + warp_n * 32 + j * 8 + tig * 2;
            float bb0 = __ldg(&b1[c0]), bb1 = __ldg(&b1[c0 + 1]);
            float v0 = acc[i][j][0] + bb0;
            float v1 = acc[i][j][1] + bb1;
            float v2 = acc[i][j][2] + bb0;
            float v3 = acc[i][j][3] + bb1;
            v0 = v0 / (1.f + __expf(-v0));
            v1 = v1 / (1.f + __expf(-v1));
            v2 = v2 / (1.f + __expf(-v2));
            v3 = v3 / (1.f + __expf(-v3));
            *reinterpret_cast<unsigned*>(&g_h[(size_t)r0 * D + c0]) =
                h2u(__floats2half2_rn(v0, v1));
            *reinterpret_cast<unsigned*>(&g_h[(size_t)(r0 + 8) * D + c0]) =
                h2u(__floats2half2_rn(v2, v3));
        }
    }
}

// ---------------------------------------------------------------------------
// GEMM2 + bias + LayerNorm fused.  BM=64 BN=512 (full rows) BK=32, fp16 mma.
// 512 thr, 16 warps (2m x 8n), warp tile 32x64. ldmatrix frag loads.
// 4-stage cp.async, issue-before-mma.
// ---------------------------------------------------------------------------
#define G2_RS 20
#define G2_ATILE (64 * G2_RS)     // 1280 words
#define G2_BTILE (512 * G2_RS)    // 10240 words
#define G2_STW (G2_ATILE + G2_BTILE)
__global__ __launch_bounds__(512, 1) void gemm2_ln_f16(const float* __restrict__ b2,
                                                       const float* __restrict__ gamma,
                                                       const float* __restrict__ beta,
                                                       float* __restrict__ out) {
    extern __shared__ unsigned smw[];
    __shared__ float mean_s[64], rstd_s[64];

    int tid = threadIdx.x, lane = tid & 31, wid = tid >> 5;
    int warp_m = wid >> 3, warp_n = wid & 7;
    int g = lane >> 2, tig = lane & 3;
    int bm = blockIdx.x;

    unsigned sbase = (unsigned)__cvta_generic_to_shared(smw);
    int t4 = lane >> 3, rr = lane & 7;
    int a_row = (t4 & 1) * 8 + rr;
    int a_wof = (t4 >> 1) * 4;
    int b_row = (t4 >> 1) * 8 + rr;
    int b_wof = (t4 & 1) * 4;

    const __half* aSrc = g_h + (size_t)(bm * 64) * D;

    float acc[2][8][4] = {};

#define G2_ISSUE(kt, st)                                                         \
    {                                                                            \
        unsigned* base = smw + (st) * G2_STW;                                    \
        if (tid < 256) {                                                         \
            int row = tid >> 2, wq = (tid & 3) * 4;                              \
            cp16(base + row * G2_RS + wq,                                        \
                 aSrc + (size_t)row * D + (kt) * 32 + wq * 2);                   \
        }                                                                        \
        _Pragma("unroll")                                                        \
        for (int t = 0; t < 4; ++t) {                                            \
            int idx = tid + t * 512;                                             \
            int row = idx >> 2, wq = (idx & 3) * 4;                              \
            cp16(base + G2_ATILE + row * G2_RS + wq,                             \
                 g_w2t + (size_t)row * D + (kt) * 32 + wq * 2);                  \
        }                                                                        \
        CP_COMMIT();                                                             \
    }

    G2_ISSUE(0, 0);
    G2_ISSUE(1, 1);
    G2_ISSUE(2, 2);

    for (int kt = 0; kt < 16; ++kt) {
        CP_WAIT2();
        __syncthreads();
        if (kt + 3 < 16) {
            G2_ISSUE(kt + 3, (kt + 3) & 3);
        } else {
            CP_COMMIT();
        }
        unsigned cbase = sbase + ((kt & 3) * G2_STW) * 4;
#pragma unroll
        for (int ks = 0; ks < 2; ++ks) {
            unsigned a[2][4], b[8][2];
#pragma unroll
            for (int i = 0; i < 2; ++i) {
                unsigned addr = cbase +
                    ((warp_m * 32 + i * 16 + a_row) * G2_RS + ks * 8 + a_wof) * 4;
                ldsm4(a[i][0], a[i][1], a[i][2], a[i][3], addr);
            }
#pragma unroll
            for (int j2 = 0; j2 < 4; ++j2) {
                unsigned addr = cbase +
                    (G2_ATILE + (warp_n * 64 + j2 * 16 + b_row) * G2_RS + ks * 8 + b_wof) * 4;
                ldsm4(b[2 * j2][0], b[2 * j2][1], b[2 * j2 + 1][0], b[2 * j2 + 1][1], addr);
            }
#pragma unroll
            for (int i = 0; i < 2; ++i)
#pragma unroll
                for (int j = 0; j < 8; ++j)
                    mma_f16(acc[i][j], a[i], b[j]);
        }
    }

    // bias + per-row partial sums
    float rsum[4] = {0.f, 0.f, 0.f, 0.f};
    float rsq[4]  = {0.f, 0.f, 0.f, 0.f};
#pragma unroll
    for (int i = 0; i < 2; ++i)
#pragma unroll
        for (int j = 0; j < 8; ++j) {
            int c0 = warp_n * 64 + j * 8 + tig * 2;
            float bb0 = __ldg(&b2[c0]), bb1 = __ldg(&b2[c0 + 1]);
            float v0 = acc[i][j][0] + bb0;
            float v1 = acc[i][j][1] + bb1;
            float v2 = acc[i][j][2] + bb0;
            float v3 = acc[i][j][3] + bb1;
            acc[i][j][0] = v0; acc[i][j][1] = v1;
            acc[i][j][2] = v2; acc[i][j][3] = v3;
            rsum[i * 2 + 0] += v0 + v1;
            rsq [i * 2 + 0] += v0 * v0 + v1 * v1;
            rsum[i * 2 + 1] += v2 + v3;
            rsq [i * 2 + 1] += v2 * v2 + v3 * v3;
        }
#pragma unroll
    for (int h = 0; h < 4; ++h) {
        rsum[h] += __shfl_xor_sync(0xffffffffu, rsum[h], 1);
        rsum[h] += __shfl_xor_sync(0xffffffffu, rsum[h], 2);
        rsq[h]  += __shfl_xor_sync(0xffffffffu, rsq[h], 1);
        rsq[h]  += __shfl_xor_sync(0xffffffffu, rsq[h], 2);
    }
    __syncthreads();  // mainloop smem reads done before reuse
    float* red = reinterpret_cast<float*>(smw);  // 1024 floats
    if (tig == 0) {
#pragma unroll
        for (int h = 0; h < 4; ++h) {
            int row = warp_m * 32 + (h >> 1) * 16 + (h & 1) * 8 + g;
            red[row * 8 + warp_n] = rsum[h];
            red[512 + row * 8 + warp_n] = rsq[h];
        }
    }
    __syncthreads();
    if (tid < 64) {
        float s = 0.f, q = 0.f;
#pragma unroll
        for (int w = 0; w < 8; ++w) {
            s += red[tid * 8 + w];
            q += red[512 + tid * 8 + w];
        }
        float mean = s * (1.0f / 512.0f);
        float var = q * (1.0f / 512.0f) - mean * mean;
        mean_s[tid] = mean;
        rstd_s[tid] = rsqrtf(var + 1e-5f);
    }
    __syncthreads();

#pragma unroll
    for (int i = 0; i < 2; ++i)
#pragma unroll
        for (int hi = 0; hi < 2; ++hi) {
            int row = warp_m * 32 + i * 16 + hi * 8 + g;
            int grow = bm * 64 + row;
            if (grow < NNODES) {
                float mean = mean_s[row], rstd = rstd_s[row];
#pragma unroll
                for (int j = 0; j < 8; ++j) {
                    int c0 = warp_n * 64 + j * 8 + tig * 2;
                    float ga0 = __ldg(&gamma[c0]), ga1 = __ldg(&gamma[c0 + 1]);
                    float be0 = __ldg(&beta[c0]),  be1 = __ldg(&beta[c0 + 1]);
                    float y0 = (acc[i][j][hi * 2 + 0] - mean) * rstd * ga0 + be0;
                    float y1 = (acc[i][j][hi * 2 + 1] - mean) * rstd * ga1 + be1;
                    *reinterpret_cast<float2*>(&out[(size_t)grow * D + c0]) =
                        make_float2(y0, y1);
                }
            }
        }
}

// ---------------------------------------------------------------------------
extern "C" void kernel_launch(void* const* d_in, const int* in_sizes, int n_in,
                              void* d_out, int out_size) {
    const float* node       = (const float*)d_in[0];
    const int*   edge_index = (const int*)  d_in[1];
    const float* edge_attr  = (const float*)d_in[2];
    const float* W1         = (const float*)d_in[3];
    const float* b1         = (const float*)d_in[4];
    const float* W2         = (const float*)d_in[5];
    const float* b2         = (const float*)d_in[6];
    const float* gamma      = (const float*)d_in[7];
    const float* beta       = (const float*)d_in[8];
    float* out = (float*)d_out;

    int smem1 = 4 * G1_STW * sizeof(unsigned);  // 81920 B
    int smem2 = 4 * G2_STW * sizeof(unsigned);  // 184320 B
    cudaFuncSetAttribute(gemm1_f16,    cudaFuncAttributeMaxDynamicSharedMemorySize, smem1);
    cudaFuncSetAttribute(gemm2_ln_f16, cudaFuncAttributeMaxDynamicSharedMemorySize, smem2);

    size_t n4 = (size_t)NNODES * D / 4;
    zero_kernel<<<(unsigned)((n4 + 255) / 256), 256>>>();
    convw1t_kernel<<<dim3(32, 16), dim3(32, 8)>>>(W1);
    convw2t_kernel<<<dim3(16, 16), dim3(32, 8)>>>(W2);
    // column-split scatter: two passes, 4 edges/thread (MLP=4)
    scatter_kernel<<<NEDGES * 64 / 1024, 256>>>(edge_attr, edge_index, 0);
    scatter_kernel<<<NEDGES * 64 / 1024, 256>>>(edge_attr, edge_index, 256);
    pack_kernel<<<MPAD, 256>>>(node);

    dim3 g1(4, MPAD / 128);
    gemm1_f16<<<g1, 256, smem1>>>(b1);

    gemm2_ln_f16<<<MPAD / 64, 512, smem2>>>(b2, gamma, beta, out);
}

// round 15
// speedup vs baseline: 1.0720x; 1.0720x over previous
#include <cuda_runtime.h>
#include <cuda_fp16.h>
#include <math.h>
#include <stdint.h>

#define NNODES 40962
#define NEDGES 327680
#define D 512
#define K1 1024
#define MPAD 41088  // 321*128

// Scratch (device globals; no allocations allowed)
__device__ float  g_edge_sum[(size_t)NNODES * D];   // 84 MB fp32 accum
__device__ __half g_x[(size_t)MPAD * K1];           // 84 MB  [node|edge_sum] fp16
__device__ __half g_h[(size_t)MPAD * D];            // 42 MB  hidden fp16
__device__ __half g_w1t[(size_t)D * K1];            // W1^T [n=512][k=1024] fp16
__device__ __half g_w2t[(size_t)D * D];             // W2^T [n=512][k=512]  fp16

__device__ __forceinline__ void mma_f16(float* c, const unsigned* a, const unsigned* b) {
    asm volatile(
        "mma.sync.aligned.m16n8k16.row.col.f32.f16.f16.f32 "
        "{%0,%1,%2,%3}, {%4,%5,%6,%7}, {%8,%9}, {%0,%1,%2,%3};\n"
        : "+f"(c[0]), "+f"(c[1]), "+f"(c[2]), "+f"(c[3])
        : "r"(a[0]), "r"(a[1]), "r"(a[2]), "r"(a[3]), "r"(b[0]), "r"(b[1]));
}
__device__ __forceinline__ void ldsm4(unsigned& r0, unsigned& r1, unsigned& r2,
                                      unsigned& r3, unsigned saddr) {
    asm volatile("ldmatrix.sync.aligned.m8n8.x4.shared.b16 {%0,%1,%2,%3}, [%4];"
                 : "=r"(r0), "=r"(r1), "=r"(r2), "=r"(r3) : "r"(saddr));
}
__device__ __forceinline__ void cp16(void* sdst, const void* gsrc) {
    unsigned sa = (unsigned)__cvta_generic_to_shared(sdst);
    asm volatile("cp.async.cg.shared.global [%0], [%1], 16;\n" :: "r"(sa), "l"(gsrc));
}
#define CP_COMMIT() asm volatile("cp.async.commit_group;\n")
#define CP_WAIT2()  asm volatile("cp.async.wait_group 2;\n")

__device__ __forceinline__ unsigned h2u(__half2 h) {
    return *reinterpret_cast<unsigned*>(&h);
}

// ---------------------------------------------------------------------------
__global__ void zero_kernel() {
    size_t i = (size_t)blockIdx.x * blockDim.x + threadIdx.x;
    size_t n4 = (size_t)NNODES * D / 4;
    if (i < n4) reinterpret_cast<float4*>(g_edge_sum)[i] = make_float4(0.f, 0.f, 0.f, 0.f);
}

// Column-split scatter, 2 edges per thread (R13 form — at REDG/L2-atomic floor).
__global__ __launch_bounds__(256) void scatter_kernel(const float* __restrict__ edge_attr,
                                                      const int* __restrict__ edge_index,
                                                      int col0) {
    int idx = blockIdx.x * 256 + threadIdx.x;
    int p = idx >> 6;              // edge pair
    int t = idx & 63;              // float4 slot within the 256-col half
    int e0 = p * 2;
    int2 rr = *reinterpret_cast<const int2*>(edge_index + NEDGES + e0);
    const float* s0 = edge_attr + (size_t)e0 * D + col0 + t * 4;
    float4 v0 = __ldcs(reinterpret_cast<const float4*>(s0));
    float4 v1 = __ldcs(reinterpret_cast<const float4*>(s0 + D));
    float* d0 = g_edge_sum + (size_t)rr.x * D + col0 + t * 4;
    float* d1 = g_edge_sum + (size_t)rr.y * D + col0 + t * 4;
    asm volatile("red.global.add.v4.f32 [%0], {%1,%2,%3,%4};\n"
                 :: "l"(d0), "f"(v0.x), "f"(v0.y), "f"(v0.z), "f"(v0.w) : "memory");
    asm volatile("red.global.add.v4.f32 [%0], {%1,%2,%3,%4};\n"
                 :: "l"(d1), "f"(v1.x), "f"(v1.y), "f"(v1.z), "f"(v1.w) : "memory");
}

// Fused weight transpose+convert: W1 [k=1024][n=512] -> g_w1t [n][k] fp16
// and W2 [k=512][n=512] -> g_w2t [n][k] fp16, one launch.
// grid (48, 16): bx<32 -> W1 k-tile bx; bx>=32 -> W2 k-tile (bx-32).
__global__ void convw_kernel(const float* __restrict__ W1, const float* __restrict__ W2) {
    __shared__ float t[32][33];
    int bx = blockIdx.x;
    int by = blockIdx.y;   // n tile (16)
    int x = threadIdx.x, y = threadIdx.y;  // 32 x 8
    if (bx < 32) {
#pragma unroll
        for (int i = 0; i < 32; i += 8)
            t[y + i][x] = W1[(size_t)(bx * 32 + y + i) * D + by * 32 + x];
        __syncthreads();
#pragma unroll
        for (int i = 0; i < 32; i += 8)
            g_w1t[(size_t)(by * 32 + y + i) * K1 + bx * 32 + x] = __float2half_rn(t[x][y + i]);
    } else {
        int kx = bx - 32;  // 0..15
#pragma unroll
        for (int i = 0; i < 32; i += 8)
            t[y + i][x] = W2[(size_t)(kx * 32 + y + i) * D + by * 32 + x];
        __syncthreads();
#pragma unroll
        for (int i = 0; i < 32; i += 8)
            g_w2t[(size_t)(by * 32 + y + i) * D + kx * 32 + x] = __float2half_rn(t[x][y + i]);
    }
}

// g_x[r] = fp16([node[r] | edge_sum[r]]), zero for pad rows.
// 128 threads per row, each thread loads one float4 from EACH half (MLP=2).
// Block = 2 rows.
__global__ __launch_bounds__(256) void pack_kernel(const float* __restrict__ node) {
    int tid = threadIdx.x;
    int r = blockIdx.x * 2 + (tid >> 7);
    int t = tid & 127;
    int c = t * 4;
    float4 va = make_float4(0.f, 0.f, 0.f, 0.f);
    float4 vb = va;
    if (r < NNODES) {
        va = *reinterpret_cast<const float4*>(node + (size_t)r * D + c);
        vb = *reinterpret_cast<const float4*>(g_edge_sum + (size_t)r * D + c);
    }
    uint2 oa = make_uint2(h2u(__floats2half2_rn(va.x, va.y)),
                          h2u(__floats2half2_rn(va.z, va.w)));
    uint2 ob = make_uint2(h2u(__floats2half2_rn(vb.x, vb.y)),
                          h2u(__floats2half2_rn(vb.z, vb.w)));
    *reinterpret_cast<uint2*>(g_x + (size_t)r * K1 + c) = oa;
    *reinterpret_cast<uint2*>(g_x + (size_t)r * K1 + D + c) = ob;
}

// ---------------------------------------------------------------------------
// GEMM1: h = silu(g_x @ W1 + b1)   M=MPAD K=1024 N=512, fp16 mma m16n8k16.
// BM=128 BN=128 BK=32. 256 thr, 8 warps (2m x 4n), warp tile 64x32.
// A,B smem tiles: [128 rows][16 half2 words], word stride 20.
// ldmatrix frag loads. 4-stage cp.async, issue AFTER mma (R13 form).
// ---------------------------------------------------------------------------
#define G1_RS 20                  // row stride in 32-bit words
#define G1_TILE (128 * G1_RS)     // words per operand tile
#define G1_STW (2 * G1_TILE)      // words per stage (A+B)
__global__ __launch_bounds__(256, 2) void gemm1_f16(const float* __restrict__ b1) {
    extern __shared__ unsigned smw[];
    int tid = threadIdx.x, lane = tid & 31, wid = tid >> 5;
    int warp_m = wid >> 2, warp_n = wid & 3;
    int g = lane >> 2, tig = lane & 3;
    int bx = blockIdx.x, by = blockIdx.y;

    unsigned sbase = (unsigned)__cvta_generic_to_shared(smw);

    // ldmatrix lane-address components
    int t4 = lane >> 3, rr = lane & 7;
    int a_row = (t4 & 1) * 8 + rr;     // row offset within mtile
    int a_wof = (t4 >> 1) * 4;         // word offset within ks group
    int b_row = (t4 >> 1) * 8 + rr;    // row offset within ntile-pair
    int b_wof = (t4 & 1) * 4;

    const __half* aSrc = g_x + (size_t)(by * 128) * K1;
    const __half* bSrc = g_w1t + (size_t)(bx * 128) * K1;

    float acc[4][4][4] = {};

#define G1_ISSUE(kt, st)                                                         \
    {                                                                            \
        unsigned* base = smw + (st) * G1_STW;                                    \
        _Pragma("unroll")                                                        \
        for (int t = 0; t < 2; ++t) {                                            \
            int idx = tid + t * 256;                                             \
            int row = idx >> 2, wq = (idx & 3) * 4;                              \
            cp16(base + row * G1_RS + wq,                                        \
                 aSrc + (size_t)row * K1 + (kt) * 32 + wq * 2);                  \
        }                                                                        \
        _Pragma("unroll")                                                        \
        for (int t = 0; t < 2; ++t) {                                            \
            int idx = tid + t * 256;                                             \
            int row = idx >> 2, wq = (idx & 3) * 4;                              \
            cp16(base + G1_TILE + row * G1_RS + wq,                              \
                 bSrc + (size_t)row * K1 + (kt) * 32 + wq * 2);                  \
        }                                                                        \
        CP_COMMIT();                                                             \
    }

    G1_ISSUE(0, 0);
    G1_ISSUE(1, 1);
    G1_ISSUE(2, 2);

    for (int kt = 0; kt < 32; ++kt) {
        CP_WAIT2();
        __syncthreads();
        unsigned cbase = sbase + ((kt & 3) * G1_STW) * 4;
#pragma unroll
        for (int ks = 0; ks < 2; ++ks) {
            unsigned a[4][4], b[4][2];
#pragma unroll
            for (int i = 0; i < 4; ++i) {
                unsigned addr = cbase +
                    ((warp_m * 64 + i * 16 + a_row) * G1_RS + ks * 8 + a_wof) * 4;
                ldsm4(a[i][0], a[i][1], a[i][2], a[i][3], addr);
            }
#pragma unroll
            for (int j2 = 0; j2 < 2; ++j2) {
                unsigned addr = cbase +
                    (G1_TILE + (warp_n * 32 + j2 * 16 + b_row) * G1_RS + ks * 8 + b_wof) * 4;
                ldsm4(b[2 * j2][0], b[2 * j2][1], b[2 * j2 + 1][0], b[2 * j2 + 1][1], addr);
            }
#pragma unroll
            for (int i = 0; i < 4; ++i)
#pragma unroll
                for (int j = 0; j < 4; ++j)
                    mma_f16(acc[i][j], a[i], b[j]);
        }
        if (kt + 3 < 32) {
            G1_ISSUE(kt + 3, (kt + 3) & 3);
        } else {
            CP_COMMIT();
        }
    }

    // epilogue: bias + silu -> fp16 g_h
#pragma unroll
    for (int i = 0; i < 4; ++i) {
        int r0 = by * 128 + warp_m * 64 + i * 16 + g;
#pragma unroll
        for (int j = 0; j < 4; ++j) {
            int c0 = bx * 128 + warp_n * 32 + j * 8 + tig * 2;
            float bb0 = __ldg(&b1[c0]), bb1 = __ldg(&b1[c0 + 1]);
            float v0 = acc[i][j][0] + bb0;
            float v1 = acc[i][j][1] + bb1;
            float v2 = acc[i][j][2] + bb0;
            float v3 = acc[i][j][3] + bb1;
            v0 = v0 / (1.f + __expf(-v0));
            v1 = v1 / (1.f + __expf(-v1));
            v2 = v2 / (1.f + __expf(-v2));
            v3 = v3 / (1.f + __expf(-v3));
            *reinterpret_cast<unsigned*>(&g_h[(size_t)r0 * D + c0]) =
                h2u(__floats2half2_rn(v0, v1));
            *reinterpret_cast<unsigned*>(&g_h[(size_t)(r0 + 8) * D + c0]) =
                h2u(__floats2half2_rn(v2, v3));
        }
    }
}

// ---------------------------------------------------------------------------
// GEMM2 + bias + LayerNorm fused.  BM=64 BN=512 (full rows) BK=32, fp16 mma.
// 512 thr, 16 warps (2m x 8n), warp tile 32x64. ldmatrix frag loads.
// 4-stage cp.async, issue AFTER mma (R13 form).
// ---------------------------------------------------------------------------
#define G2_RS 20
#define G2_ATILE (64 * G2_RS)     // 1280 words
#define G2_BTILE (512 * G2_RS)    // 10240 words
#define G2_STW (G2_ATILE + G2_BTILE)
__global__ __launch_bounds__(512, 1) void gemm2_ln_f16(const float* __restrict__ b2,
                                                       const float* __restrict__ gamma,
                                                       const float* __restrict__ beta,
                                                       float* __restrict__ out) {
    extern __shared__ unsigned smw[];
    __shared__ float mean_s[64], rstd_s[64];

    int tid = threadIdx.x, lane = tid & 31, wid = tid >> 5;
    int warp_m = wid >> 3, warp_n = wid & 7;
    int g = lane >> 2, tig = lane & 3;
    int bm = blockIdx.x;

    unsigned sbase = (unsigned)__cvta_generic_to_shared(smw);
    int t4 = lane >> 3, rr = lane & 7;
    int a_row = (t4 & 1) * 8 + rr;
    int a_wof = (t4 >> 1) * 4;
    int b_row = (t4 >> 1) * 8 + rr;
    int b_wof = (t4 & 1) * 4;

    const __half* aSrc = g_h + (size_t)(bm * 64) * D;

    float acc[2][8][4] = {};

#define G2_ISSUE(kt, st)                                                         \
    {                                                                            \
        unsigned* base = smw + (st) * G2_STW;                                    \
        if (tid < 256) {                                                         \
            int row = tid >> 2, wq = (tid & 3) * 4;                              \
            cp16(base + row * G2_RS + wq,                                        \
                 aSrc + (size_t)row * D + (kt) * 32 + wq * 2);                   \
        }                                                                        \
        _Pragma("unroll")                                                        \
        for (int t = 0; t < 4; ++t) {                                            \
            int idx = tid + t * 512;                                             \
            int row = idx >> 2, wq = (idx & 3) * 4;                              \
            cp16(base + G2_ATILE + row * G2_RS + wq,                             \
                 g_w2t + (size_t)row * D + (kt) * 32 + wq * 2);                  \
        }                                                                        \
        CP_COMMIT();                                                             \
    }

    G2_ISSUE(0, 0);
    G2_ISSUE(1, 1);
    G2_ISSUE(2, 2);

    for (int kt = 0; kt < 16; ++kt) {
        CP_WAIT2();
        __syncthreads();
        unsigned cbase = sbase + ((kt & 3) * G2_STW) * 4;
#pragma unroll
        for (int ks = 0; ks < 2; ++ks) {
            unsigned a[2][4], b[8][2];
#pragma unroll
            for (int i = 0; i < 2; ++i) {
                unsigned addr = cbase +
                    ((warp_m * 32 + i * 16 + a_row) * G2_RS + ks * 8 + a_wof) * 4;
                ldsm4(a[i][0], a[i][1], a[i][2], a[i][3], addr);
            }
#pragma unroll
            for (int j2 = 0; j2 < 4; ++j2) {
                unsigned addr = cbase +
                    (G2_ATILE + (warp_n * 64 + j2 * 16 + b_row) * G2_RS + ks * 8 + b_wof) * 4;
                ldsm4(b[2 * j2][0], b[2 * j2][1], b[2 * j2 + 1][0], b[2 * j2 + 1][1], addr);
            }
#pragma unroll
            for (int i = 0; i < 2; ++i)
#pragma unroll
                for (int j = 0; j < 8; ++j)
                    mma_f16(acc[i][j], a[i], b[j]);
        }
        if (kt + 3 < 16) {
            G2_ISSUE(kt + 3, (kt + 3) & 3);
        } else {
            CP_COMMIT();
        }
    }

    // bias + per-row partial sums
    float rsum[4] = {0.f, 0.f, 0.f, 0.f};
    float rsq[4]  = {0.f, 0.f, 0.f, 0.f};
#pragma unroll
    for (int i = 0; i < 2; ++i)
#pragma unroll
        for (int j = 0; j < 8; ++j) {
            int c0 = warp_n * 64 + j * 8 + tig * 2;
            float bb0 = __ldg(&b2[c0]), bb1 = __ldg(&b2[c0 + 1]);
            float v0 = acc[i][j][0] + bb0;
            float v1 = acc[i][j][1] + bb1;
            float v2 = acc[i][j][2] + bb0;
            float v3 = acc[i][j][3] + bb1;
            acc[i][j][0] = v0; acc[i][j][1] = v1;
            acc[i][j][2] = v2; acc[i][j][3] = v3;
            rsum[i * 2 + 0] += v0 + v1;
            rsq [i * 2 + 0] += v0 * v0 + v1 * v1;
            rsum[i * 2 + 1] += v2 + v3;
            rsq [i * 2 + 1] += v2 * v2 + v3 * v3;
        }
#pragma unroll
    for (int h = 0; h < 4; ++h) {
        rsum[h] += __shfl_xor_sync(0xffffffffu, rsum[h], 1);
        rsum[h] += __shfl_xor_sync(0xffffffffu, rsum[h], 2);
        rsq[h]  += __shfl_xor_sync(0xffffffffu, rsq[h], 1);
        rsq[h]  += __shfl_xor_sync(0xffffffffu, rsq[h], 2);
    }
    __syncthreads();  // mainloop smem reads done before reuse
    float* red = reinterpret_cast<float*>(smw);  // 1024 floats
    if (tig == 0) {
#pragma unroll
        for (int h = 0; h < 4; ++h) {
            int row = warp_m * 32 + (h >> 1) * 16 + (h & 1) * 8 + g;
            red[row * 8 + warp_n] = rsum[h];
            red[512 + row * 8 + warp_n] = rsq[h];
        }
    }
    __syncthreads();
    if (tid < 64) {
        float s = 0.f, q = 0.f;
#pragma unroll
        for (int w = 0; w < 8; ++w) {
            s += red[tid * 8 + w];
            q += red[512 + tid * 8 + w];
        }
        float mean = s * (1.0f / 512.0f);
        float var = q * (1.0f / 512.0f) - mean * mean;
        mean_s[tid] = mean;
        rstd_s[tid] = rsqrtf(var + 1e-5f);
    }
    __syncthreads();

#pragma unroll
    for (int i = 0; i < 2; ++i)
#pragma unroll
        for (int hi = 0; hi < 2; ++hi) {
            int row = warp_m * 32 + i * 16 + hi * 8 + g;
            int grow = bm * 64 + row;
            if (grow < NNODES) {
                float mean = mean_s[row], rstd = rstd_s[row];
#pragma unroll
                for (int j = 0; j < 8; ++j) {
                    int c0 = warp_n * 64 + j * 8 + tig * 2;
                    float ga0 = __ldg(&gamma[c0]), ga1 = __ldg(&gamma[c0 + 1]);
                    float be0 = __ldg(&beta[c0]),  be1 = __ldg(&beta[c0 + 1]);
                    float y0 = (acc[i][j][hi * 2 + 0] - mean) * rstd * ga0 + be0;
                    float y1 = (acc[i][j][hi * 2 + 1] - mean) * rstd * ga1 + be1;
                    *reinterpret_cast<float2*>(&out[(size_t)grow * D + c0]) =
                        make_float2(y0, y1);
                }
            }
        }
}

// ---------------------------------------------------------------------------
extern "C" void kernel_launch(void* const* d_in, const int* in_sizes, int n_in,
                              void* d_out, int out_size) {
    const float* node       = (const float*)d_in[0];
    const int*   edge_index = (const int*)  d_in[1];
    const float* edge_attr  = (const float*)d_in[2];
    const float* W1         = (const float*)d_in[3];
    const float* b1         = (const float*)d_in[4];
    const float* W2         = (const float*)d_in[5];
    const float* b2         = (const float*)d_in[6];
    const float* gamma      = (const float*)d_in[7];
    const float* beta       = (const float*)d_in[8];
    float* out = (float*)d_out;

    int smem1 = 4 * G1_STW * sizeof(unsigned);  // 81920 B
    int smem2 = 4 * G2_STW * sizeof(unsigned);  // 184320 B
    cudaFuncSetAttribute(gemm1_f16,    cudaFuncAttributeMaxDynamicSharedMemorySize, smem1);
    cudaFuncSetAttribute(gemm2_ln_f16, cudaFuncAttributeMaxDynamicSharedMemorySize, smem2);

    size_t n4 = (size_t)NNODES * D / 4;
    zero_kernel<<<(unsigned)((n4 + 255) / 256), 256>>>();
    convw_kernel<<<dim3(48, 16), dim3(32, 8)>>>(W1, W2);
    // column-split scatter: two passes, 2 edges/thread (MLP=2)
    scatter_kernel<<<NEDGES * 64 / 512, 256>>>(edge_attr, edge_index, 0);
    scatter_kernel<<<NEDGES * 64 / 512, 256>>>(edge_attr, edge_index, 256);
    pack_kernel<<<MPAD / 2, 256>>>(node);

    dim3 g1(4, MPAD / 128);
    gemm1_f16<<<g1, 256, smem1>>>(b1);

    gemm2_ln_f16<<<MPAD / 64, 512, smem2>>>(b2, gamma, beta, out);
}